// round 5
// baseline (speedup 1.0000x reference)
#include <cuda_runtime.h>
#include <math.h>

#define BB   16
#define LL   4096
#define DD   512
#define LP1  4097
#define D4   128        // D/4 float4 lanes per row
#define CH   8          // l rows per block (512 chunk blocks + 1 epilogue)

// ---------------------------------------------------------------------------
// c[d] = 100^(-(d - d%2)/512) + (pi/2)*(d%2) computed as r^(d>>1) with
// r = 100^(-1/256) via binary exponentiation (pure DMUL, ~2.5e-10 rel err,
// below f32 ulp of the reference coefficient).
// ---------------------------------------------------------------------------
__device__ __forceinline__ float coef(int d) {
    const double R = 0.982171889188039;   // 100^(-1/256)
    double f = 1.0, p = R;
    int k = d >> 1;                        // 0..255
#pragma unroll
    for (int i = 0; i < 8; i++) {
        if (k & 1) f *= p;
        p *= p;
        k >>= 1;
    }
    return (float)f + ((d & 1) ? 1.57079632679489662f : 0.0f);
}

// ---------------------------------------------------------------------------
// Fused kernel.
//  Block 0..511: l-chunk [8*bid, 8*bid+8).
//    Phase 1: thread d builds emb[ll][d] = sin((l0+ll)*c[d]) in smem via
//             angle-addition recurrence anchored by one sincosf pair.
//    Phase 2: stream all 16 batch rows for this chunk:
//             out = tok+emb (l<len) | cls (l==len) | 0 (else).
//  Block 512: epilogue — the 16 rows at l = 4096 (cls or zero only).
// ---------------------------------------------------------------------------
__global__ void __launch_bounds__(512)
fused_kernel(const float4* __restrict__ tok,
             const int*    __restrict__ lengths,
             const float4* __restrict__ cls,
             float4*       __restrict__ out)
{
    int t = threadIdx.x;
    int d4 = t & (D4 - 1);                 // 0..127
    float4 clsv = __ldg(&cls[d4]);

    if (blockIdx.x == LL / CH) {           // ---- epilogue: rows l = LL ----
        int g = t >> 7;                    // 0..3
#pragma unroll
        for (int i = 0; i < 4; i++) {
            int b = g * 4 + i;
            int len = __ldg(&lengths[b]);
            float4 v = (len == LL) ? clsv : make_float4(0.f, 0.f, 0.f, 0.f);
            __stcs(&out[((size_t)b * LP1 + LL) * D4 + d4], v);
        }
        return;
    }

    __shared__ float s_emb[CH * DD];       // 16 KB
    __shared__ int   s_len[BB];

    int l0 = blockIdx.x * CH;

    // ---- phase 1: emb rows for this chunk (thread t == dimension d) ----
    {
        float c = coef(t);
        float s, cs, sd, cd;
        sincosf((float)l0 * c, &s, &cs);   // exact anchor at chunk start
        sincosf(c, &sd, &cd);              // per-step rotation
#pragma unroll
        for (int k = 0; k < CH; k++) {
            s_emb[k * DD + t] = s;
            float ns = fmaf(s,  cd, cs * sd);
            float nc = fmaf(cs, cd, -(s * sd));
            s = ns; cs = nc;
        }
    }
    if (t < BB) s_len[t] = lengths[t];
    __syncthreads();

    // ---- phase 2: stream 16 batch elements x 8 rows ----
    int rq = t >> 7;                       // row quadrant 0..3
    const float4* se = reinterpret_cast<const float4*>(s_emb);

#pragma unroll 1
    for (int b = 0; b < BB; b++) {
        int len = s_len[b];
        size_t orow = (size_t)b * LP1 + l0;
        size_t trow = (size_t)b * LL  + l0;
#pragma unroll
        for (int j = 0; j < CH / 4; j++) {
            int ll = rq + j * 4;
            int l  = l0 + ll;
            float4 v;
            if (l < len) {
                float4 tk = __ldcs(&tok[(trow + ll) * D4 + d4]);
                float4 em = se[ll * D4 + d4];
                v.x = tk.x + em.x;
                v.y = tk.y + em.y;
                v.z = tk.z + em.z;
                v.w = tk.w + em.w;
            } else if (l == len) {
                v = clsv;
            } else {
                v = make_float4(0.f, 0.f, 0.f, 0.f);
            }
            __stcs(&out[(orow + ll) * D4 + d4], v);
        }
    }
}

// ---------------------------------------------------------------------------
extern "C" void kernel_launch(void* const* d_in, const int* in_sizes, int n_in,
                              void* d_out, int out_size)
{
    const float4* tok     = (const float4*)d_in[0];   // tokens  [B,L,D] f32
    const int*    lengths = (const int*)   d_in[1];   // lengths [B]    i32
    const float4* cls     = (const float4*)d_in[2];   // cls     [D]    f32
    float4*       out     = (float4*)d_out;           // [B,L+1,D] f32

    fused_kernel<<<LL / CH + 1, 512>>>(tok, lengths, cls, out);
}

// round 7
// speedup vs baseline: 1.0116x; 1.0116x over previous
#include <cuda_runtime.h>
#include <math.h>

#define BB   16
#define LL   4096
#define DD   512
#define LP1  4097
#define D4   128        // D/4 float4 lanes per row
#define CH   8          // l rows per block (512 chunk blocks + 1 epilogue)
#define NT   256        // threads per block

// ---------------------------------------------------------------------------
// c[d] = 100^(-(d - d%2)/512) + (pi/2)*(d%2) computed as r^(d>>1) with
// r = 100^(-1/256) via binary exponentiation (pure DMUL, ~2.5e-10 rel err,
// below f32 ulp of the reference coefficient).
// ---------------------------------------------------------------------------
__device__ __forceinline__ float coef(int d) {
    const double R = 0.982171889188039;   // 100^(-1/256)
    double f = 1.0, p = R;
    int k = d >> 1;                        // 0..255
#pragma unroll
    for (int i = 0; i < 8; i++) {
        if (k & 1) f *= p;
        p *= p;
        k >>= 1;
    }
    return (float)f + ((d & 1) ? 1.57079632679489662f : 0.0f);
}

// ---------------------------------------------------------------------------
// Fused kernel, 256 threads.
//  Blocks 0..511: l-chunk [8*bid, 8*bid+8).
//   Phase 1: build emb rows for the chunk in smem (each thread: 2 d-lanes,
//            angle-addition recurrence anchored by sincosf).
//   Phase 2: stream all 16 batch elements; loads batched 8-deep per thread
//            (2 b x 4 rows) before the matching stores -> MLP ~8.
//  Block 512: epilogue — the 16 rows at l = 4096 (cls or zero only).
// ---------------------------------------------------------------------------
__global__ void __launch_bounds__(NT)
fused_kernel(const float4* __restrict__ tok,
             const int*    __restrict__ lengths,
             const float4* __restrict__ cls,
             float4*       __restrict__ out)
{
    int t    = threadIdx.x;
    int d4   = t & (D4 - 1);               // 0..127
    int slot = t >> 7;                     // 0..1
    float4 clsv = __ldg(&cls[d4]);
    const float4 zero = make_float4(0.f, 0.f, 0.f, 0.f);

    if (blockIdx.x == LL / CH) {           // ---- epilogue: rows l = LL ----
#pragma unroll
        for (int i = 0; i < BB / 2; i++) {
            int b = i * 2 + slot;
            int len = __ldg(&lengths[b]);
            float4 v = (len == LL) ? clsv : zero;
            __stcs(&out[((size_t)b * LP1 + LL) * D4 + d4], v);
        }
        return;
    }

    __shared__ float s_emb[CH * DD];       // 16 KB
    __shared__ int   s_len[BB];

    int l0 = blockIdx.x * CH;

    // ---- phase 1: emb rows for this chunk (2 d-lanes per thread) ----
#pragma unroll
    for (int h = 0; h < 2; h++) {
        int d = t + h * NT;
        float c = coef(d);
        float s, cs, sd, cd;
        sincosf((float)l0 * c, &s, &cs);   // exact anchor at chunk start
        sincosf(c, &sd, &cd);              // per-step rotation
#pragma unroll
        for (int k = 0; k < CH; k++) {
            s_emb[k * DD + d] = s;
            float ns = fmaf(s,  cd, cs * sd);
            float nc = fmaf(cs, cd, -(s * sd));
            s = ns; cs = nc;
        }
    }
    if (t < BB) s_len[t] = lengths[t];
    __syncthreads();

    // ---- phase 2: stream 16 batch elements, 8 loads in flight ----
    const float4* se = reinterpret_cast<const float4*>(s_emb);

#pragma unroll 1
    for (int b0 = 0; b0 < BB; b0 += 2) {
        float4 tk[8];
        int    st[8];                      // 0=zero, 1=tok+emb, 2=cls

        // batch the 8 independent (predicated) loads
#pragma unroll
        for (int u = 0; u < 2; u++) {
            int b   = b0 + u;
            int len = s_len[b];
            size_t tbase = (size_t)b * LL + l0;
#pragma unroll
            for (int j = 0; j < 4; j++) {
                int ll  = slot + j * 2;
                int idx = u * 4 + j;
                int l   = l0 + ll;
                st[idx] = (l < len) ? 1 : ((l == len) ? 2 : 0);
                if (st[idx] == 1)
                    tk[idx] = __ldcs(&tok[(tbase + ll) * D4 + d4]);
            }
        }

        // compute + store
#pragma unroll
        for (int u = 0; u < 2; u++) {
            int b = b0 + u;
            size_t obase = (size_t)b * LP1 + l0;
#pragma unroll
            for (int j = 0; j < 4; j++) {
                int ll  = slot + j * 2;
                int idx = u * 4 + j;
                float4 v;
                if (st[idx] == 1) {
                    float4 em = se[ll * D4 + d4];
                    v.x = tk[idx].x + em.x;
                    v.y = tk[idx].y + em.y;
                    v.z = tk[idx].z + em.z;
                    v.w = tk[idx].w + em.w;
                } else if (st[idx] == 2) {
                    v = clsv;
                } else {
                    v = zero;
                }
                __stcs(&out[(obase + ll) * D4 + d4], v);
            }
        }
    }
}

// ---------------------------------------------------------------------------
extern "C" void kernel_launch(void* const* d_in, const int* in_sizes, int n_in,
                              void* d_out, int out_size)
{
    const float4* tok     = (const float4*)d_in[0];   // tokens  [B,L,D] f32
    const int*    lengths = (const int*)   d_in[1];   // lengths [B]    i32
    const float4* cls     = (const float4*)d_in[2];   // cls     [D]    f32
    float4*       out     = (float4*)d_out;           // [B,L+1,D] f32

    fused_kernel<<<LL / CH + 1, NT>>>(tok, lengths, cls, out);
}

// round 8
// speedup vs baseline: 1.2538x; 1.2394x over previous
#include <cuda_runtime.h>
#include <math.h>

#define BB   16
#define LL   4096
#define DD   512
#define LP1  4097
#define D4   128        // D/4 float4 lanes per row
#define CH   8          // l rows per chunk
#define NT   256        // threads per block
#define BG   4          // batch elements per block (BB/BG b-groups)

// ---------------------------------------------------------------------------
// c[d] = 100^(-(d - d%2)/512) + (pi/2)*(d%2) computed as r^(d>>1) with
// r = 100^(-1/256) via binary exponentiation (pure DMUL, ~2.5e-10 rel err,
// below f32 ulp of the reference coefficient).
// ---------------------------------------------------------------------------
__device__ __forceinline__ float coef(int d) {
    const double R = 0.982171889188039;   // 100^(-1/256)
    double f = 1.0, p = R;
    int k = d >> 1;                        // 0..255
#pragma unroll
    for (int i = 0; i < 8; i++) {
        if (k & 1) f *= p;
        p *= p;
        k >>= 1;
    }
    return (float)f + ((d & 1) ? 1.57079632679489662f : 0.0f);
}

// ---------------------------------------------------------------------------
// Fused kernel. Grid = 512 l-chunks x 4 b-groups + 1 epilogue = 2049 CTAs.
//  Block (chunk, g):
//   Phase 1: build emb rows [l0, l0+8) in smem (2 d-lanes/thread, angle-
//            addition recurrence; recomputed per b-group — trivial cost).
//   Phase 2: stream 4 batch elements (b = 4g..4g+3); per-b loads batched
//            4-deep (MLP 4) while 2049 CTAs provide the TLP reservoir.
//  Last block: the 16 rows at l = 4096 (cls or zero only).
// ---------------------------------------------------------------------------
__global__ void __launch_bounds__(NT)
fused_kernel(const float4* __restrict__ tok,
             const int*    __restrict__ lengths,
             const float4* __restrict__ cls,
             float4*       __restrict__ out)
{
    int t    = threadIdx.x;
    int d4   = t & (D4 - 1);               // 0..127
    int slot = t >> 7;                     // 0..1
    float4 clsv = __ldg(&cls[d4]);
    const float4 zero = make_float4(0.f, 0.f, 0.f, 0.f);

    if (blockIdx.x == (LL / CH) * (BB / BG)) {   // ---- epilogue: l = LL ----
#pragma unroll
        for (int i = 0; i < BB / 2; i++) {
            int b = i * 2 + slot;
            int len = __ldg(&lengths[b]);
            float4 v = (len == LL) ? clsv : zero;
            __stcs(&out[((size_t)b * LP1 + LL) * D4 + d4], v);
        }
        return;
    }

    __shared__ float s_emb[CH * DD];       // 16 KB
    __shared__ int   s_len[BG];

    int chunk = blockIdx.x >> 2;           // 0..511
    int bg    = blockIdx.x & 3;            // 0..3
    int l0    = chunk * CH;
    int bbase = bg * BG;

    // ---- phase 1: emb rows for this chunk (2 d-lanes per thread) ----
#pragma unroll
    for (int h = 0; h < 2; h++) {
        int d = t + h * NT;
        float c = coef(d);
        float s, cs, sd, cd;
        sincosf((float)l0 * c, &s, &cs);   // exact anchor at chunk start
        sincosf(c, &sd, &cd);              // per-step rotation
#pragma unroll
        for (int k = 0; k < CH; k++) {
            s_emb[k * DD + d] = s;
            float ns = fmaf(s,  cd, cs * sd);
            float nc = fmaf(cs, cd, -(s * sd));
            s = ns; cs = nc;
        }
    }
    if (t < BG) s_len[t] = lengths[bbase + t];
    __syncthreads();

    // ---- phase 2: stream BG batch elements, 4 loads in flight per b ----
    const float4* se = reinterpret_cast<const float4*>(s_emb);

#pragma unroll 1
    for (int u = 0; u < BG; u++) {
        int b   = bbase + u;
        int len = s_len[u];
        size_t tbase = (size_t)b * LL  + l0;
        size_t obase = (size_t)b * LP1 + l0;

        float4 tk[4];
        int    stt[4];                     // 0=zero, 1=tok+emb, 2=cls
#pragma unroll
        for (int j = 0; j < 4; j++) {
            int ll = slot + j * 2;
            int l  = l0 + ll;
            stt[j] = (l < len) ? 1 : ((l == len) ? 2 : 0);
            if (stt[j] == 1)
                tk[j] = tok[(tbase + ll) * D4 + d4];
        }
#pragma unroll
        for (int j = 0; j < 4; j++) {
            int ll = slot + j * 2;
            float4 v;
            if (stt[j] == 1) {
                float4 em = se[ll * D4 + d4];
                v.x = tk[j].x + em.x;
                v.y = tk[j].y + em.y;
                v.z = tk[j].z + em.z;
                v.w = tk[j].w + em.w;
            } else if (stt[j] == 2) {
                v = clsv;
            } else {
                v = zero;
            }
            __stcs(&out[(obase + ll) * D4 + d4], v);
        }
    }
}

// ---------------------------------------------------------------------------
extern "C" void kernel_launch(void* const* d_in, const int* in_sizes, int n_in,
                              void* d_out, int out_size)
{
    const float4* tok     = (const float4*)d_in[0];   // tokens  [B,L,D] f32
    const int*    lengths = (const int*)   d_in[1];   // lengths [B]    i32
    const float4* cls     = (const float4*)d_in[2];   // cls     [D]    f32
    float4*       out     = (float4*)d_out;           // [B,L+1,D] f32

    fused_kernel<<<(LL / CH) * (BB / BG) + 1, NT>>>(tok, lengths, cls, out);
}

// round 13
// speedup vs baseline: 1.2551x; 1.0010x over previous
#include <cuda_runtime.h>
#include <math.h>

#define BB   16
#define LL   4096
#define DD   512
#define LP1  4097
#define D4   128        // D/4 float4 lanes per row
#define CH   8          // l rows per chunk
#define NT   256        // threads per block
#define BG   2          // batch elements per block (BB/BG b-groups)

// ---------------------------------------------------------------------------
// c[d] = 100^(-(d - d%2)/512) + (pi/2)*(d%2) computed as r^(d>>1) with
// r = 100^(-1/256) via binary exponentiation (pure DMUL, ~2.5e-10 rel err,
// below f32 ulp of the reference coefficient).
// ---------------------------------------------------------------------------
__device__ __forceinline__ float coef(int d) {
    const double R = 0.982171889188039;   // 100^(-1/256)
    double f = 1.0, p = R;
    int k = d >> 1;                        // 0..255
#pragma unroll
    for (int i = 0; i < 8; i++) {
        if (k & 1) f *= p;
        p *= p;
        k >>= 1;
    }
    return (float)f + ((d & 1) ? 1.57079632679489662f : 0.0f);
}

// ---------------------------------------------------------------------------
// Fused kernel. Grid = 512 l-chunks x 8 b-groups + 1 epilogue = 4097 CTAs.
//  Block (chunk, g):
//   Phase 1: build emb rows [l0, l0+8) in smem (2 d-lanes/thread, angle-
//            addition recurrence anchored by sincosf).
//   Phase 2: stream BG=2 batch elements; per-b loads batched 4-deep.
//  Last block: the 16 rows at l = 4096 (cls or zero only).
// ---------------------------------------------------------------------------
__global__ void __launch_bounds__(NT, 6)
fused_kernel(const float4* __restrict__ tok,
             const int*    __restrict__ lengths,
             const float4* __restrict__ cls,
             float4*       __restrict__ out)
{
    int t    = threadIdx.x;
    int d4   = t & (D4 - 1);               // 0..127
    int slot = t >> 7;                     // 0..1
    float4 clsv = __ldg(&cls[d4]);
    const float4 zero = make_float4(0.f, 0.f, 0.f, 0.f);

    if (blockIdx.x == (LL / CH) * (BB / BG)) {   // ---- epilogue: l = LL ----
#pragma unroll
        for (int i = 0; i < BB / 2; i++) {
            int b = i * 2 + slot;
            int len = __ldg(&lengths[b]);
            float4 v = (len == LL) ? clsv : zero;
            __stcs(&out[((size_t)b * LP1 + LL) * D4 + d4], v);
        }
        return;
    }

    __shared__ float s_emb[CH * DD];       // 16 KB
    __shared__ int   s_len[BG];

    int chunk = blockIdx.x >> 3;           // 0..511
    int bg    = blockIdx.x & 7;            // 0..7
    int l0    = chunk * CH;
    int bbase = bg * BG;

    // ---- phase 1: emb rows for this chunk (2 d-lanes per thread) ----
#pragma unroll
    for (int h = 0; h < 2; h++) {
        int d = t + h * NT;
        float c = coef(d);
        float s, cs, sd, cd;
        sincosf((float)l0 * c, &s, &cs);   // exact anchor at chunk start
        sincosf(c, &sd, &cd);              // per-step rotation
#pragma unroll
        for (int k = 0; k < CH; k++) {
            s_emb[k * DD + d] = s;
            float ns = fmaf(s,  cd, cs * sd);
            float nc = fmaf(cs, cd, -(s * sd));
            s = ns; cs = nc;
        }
    }
    if (t < BG) s_len[t] = lengths[bbase + t];
    __syncthreads();

    // ---- phase 2: stream BG batch elements, 4 loads in flight per b ----
    const float4* se = reinterpret_cast<const float4*>(s_emb);

#pragma unroll 1
    for (int u = 0; u < BG; u++) {
        int b    = bbase + u;
        int lrel = s_len[u] - l0;          // rows with ll < lrel are valid
        const float4* tp = &tok[((size_t)b * LL  + l0) * D4 + d4];
        float4*       op = &out[((size_t)b * LP1 + l0) * D4 + d4];

        float4 tk[4];
#pragma unroll
        for (int j = 0; j < 4; j++) {
            int ll = slot + j * 2;
            if (ll < lrel)
                tk[j] = tp[ll * D4];
        }
#pragma unroll
        for (int j = 0; j < 4; j++) {
            int ll = slot + j * 2;
            float4 v;
            if (ll < lrel) {
                float4 em = se[ll * D4 + d4];
                v.x = tk[j].x + em.x;
                v.y = tk[j].y + em.y;
                v.z = tk[j].z + em.z;
                v.w = tk[j].w + em.w;
            } else {
                v = (ll == lrel) ? clsv : zero;
            }
            __stcs(&op[ll * D4], v);
        }
    }
}

// ---------------------------------------------------------------------------
extern "C" void kernel_launch(void* const* d_in, const int* in_sizes, int n_in,
                              void* d_out, int out_size)
{
    const float4* tok     = (const float4*)d_in[0];   // tokens  [B,L,D] f32
    const int*    lengths = (const int*)   d_in[1];   // lengths [B]    i32
    const float4* cls     = (const float4*)d_in[2];   // cls     [D]    f32
    float4*       out     = (float4*)d_out;           // [B,L+1,D] f32

    fused_kernel<<<(LL / CH) * (BB / BG) + 1, NT>>>(tok, lengths, cls, out);
}